// round 9
// baseline (speedup 1.0000x reference)
#include <cuda_runtime.h>
#include <cuda_fp16.h>
#include <cstddef>

#define NNODES 100000
#define NEDGES 1600000
#define NFEAT  7
#define HID    128
#define NGRAPH 8
#define NCLASS 5

// ---------------------------------------------------------------------------
// Device-global scratch (allocation-free contract)
// ---------------------------------------------------------------------------
__device__ int    g_rowptr[NNODES + 1];
__device__ int    g_cur[NNODES];
__device__ int2   g_epack[NEDGES];        // CSR slot: {src, attr bits}
__device__ float  g_agg7[NNODES * NFEAT];
__device__ float  g_agg[NNODES * HID];
__device__ float  g_ha[NNODES * HID];
__device__ float  g_hb[NNODES * HID];
__device__ __half g_h16[NNODES * HID];    // fp16 copy of current h (neighbor reads)
__device__ float  g_pool[NGRAPH * HID];
__device__ float  g_cnt[NGRAPH];

// ---------------------------------------------------------------------------
// CSR build: histogram -> scan -> fill
// ---------------------------------------------------------------------------
__global__ void hist_kernel(const int* __restrict__ ei) {
    int e = blockIdx.x * blockDim.x + threadIdx.x;
    if (e < NEDGES) atomicAdd(&g_cur[ei[NEDGES + e]], 1);
}

__global__ void scan_kernel() {
    __shared__ int warp_sums[32];
    __shared__ int s_carry;
    int tid = threadIdx.x;
    int lane = tid & 31, wid = tid >> 5;
    if (tid == 0) s_carry = 0;
    __syncthreads();
    for (int base = 0; base < NNODES; base += 1024) {
        int i = base + tid;
        int v = (i < NNODES) ? g_cur[i] : 0;
        int incl = v;
#pragma unroll
        for (int o = 1; o < 32; o <<= 1) {
            int t = __shfl_up_sync(0xffffffffu, incl, o);
            if (lane >= o) incl += t;
        }
        if (lane == 31) warp_sums[wid] = incl;
        __syncthreads();
        if (wid == 0) {
            int ws = warp_sums[lane];
            int wincl = ws;
#pragma unroll
            for (int o = 1; o < 32; o <<= 1) {
                int t = __shfl_up_sync(0xffffffffu, wincl, o);
                if (lane >= o) wincl += t;
            }
            warp_sums[lane] = wincl - ws;
        }
        __syncthreads();
        int excl = incl - v + warp_sums[wid] + s_carry;
        if (i < NNODES) { g_rowptr[i] = excl; g_cur[i] = excl; }
        __syncthreads();
        if (tid == 1023) s_carry = excl + v;
        __syncthreads();
    }
    if (tid == 0) g_rowptr[NNODES] = NEDGES;
}

__global__ void fill_kernel(const int* __restrict__ ei, const float* __restrict__ ea) {
    int e = blockIdx.x * blockDim.x + threadIdx.x;
    if (e >= NEDGES) return;
    int d = ei[NEDGES + e];
    int pos = atomicAdd(&g_cur[d], 1);
    g_epack[pos] = make_int2(ei[e], __float_as_int(ea[e]));
}

// ---------------------------------------------------------------------------
// Layer 1 gather: thread per node, 7 features, 4-edge unroll
// ---------------------------------------------------------------------------
__global__ void gather7(const float* __restrict__ x, const float* __restrict__ We,
                        const float* __restrict__ be) {
    int n = blockIdx.x * blockDim.x + threadIdx.x;
    if (n >= NNODES) return;
    float w[NFEAT], bb[NFEAT], acc[NFEAT];
#pragma unroll
    for (int f = 0; f < NFEAT; f++) { w[f] = __ldg(&We[f]); bb[f] = __ldg(&be[f]); }
#pragma unroll
    for (int f = 0; f < NFEAT; f++) acc[f] = x[n * NFEAT + f];
    int beg = g_rowptr[n], end = g_rowptr[n + 1];
    int e = beg;
    for (; e + 3 < end; e += 4) {
        int2 p0 = __ldg(&g_epack[e]),     p1 = __ldg(&g_epack[e + 1]);
        int2 p2 = __ldg(&g_epack[e + 2]), p3 = __ldg(&g_epack[e + 3]);
        float a0 = __int_as_float(p0.y), a1 = __int_as_float(p1.y);
        float a2 = __int_as_float(p2.y), a3 = __int_as_float(p3.y);
        float v0[NFEAT], v1[NFEAT], v2[NFEAT], v3[NFEAT];
#pragma unroll
        for (int f = 0; f < NFEAT; f++) v0[f] = __ldg(&x[p0.x * NFEAT + f]);
#pragma unroll
        for (int f = 0; f < NFEAT; f++) v1[f] = __ldg(&x[p1.x * NFEAT + f]);
#pragma unroll
        for (int f = 0; f < NFEAT; f++) v2[f] = __ldg(&x[p2.x * NFEAT + f]);
#pragma unroll
        for (int f = 0; f < NFEAT; f++) v3[f] = __ldg(&x[p3.x * NFEAT + f]);
#pragma unroll
        for (int f = 0; f < NFEAT; f++) {
            acc[f] += fmaxf(v0[f] + fmaf(a0, w[f], bb[f]), 0.f)
                    + fmaxf(v1[f] + fmaf(a1, w[f], bb[f]), 0.f)
                    + fmaxf(v2[f] + fmaf(a2, w[f], bb[f]), 0.f)
                    + fmaxf(v3[f] + fmaf(a3, w[f], bb[f]), 0.f);
        }
    }
    for (; e < end; e++) {
        int2 p = __ldg(&g_epack[e]);
        float a = __int_as_float(p.y);
#pragma unroll
        for (int f = 0; f < NFEAT; f++)
            acc[f] += fmaxf(__ldg(&x[p.x * NFEAT + f]) + fmaf(a, w[f], bb[f]), 0.f);
    }
#pragma unroll
    for (int f = 0; f < NFEAT; f++) g_agg7[n * NFEAT + f] = acc[f];
}

// ---------------------------------------------------------------------------
// Layer 1 dense: writes fp32 h1 AND fp16 copy
// ---------------------------------------------------------------------------
__global__ void dense7(const float* __restrict__ W, const float* __restrict__ b) {
    __shared__ float sW[NFEAT * HID];
    __shared__ float sb[HID];
    __shared__ float sAgg[256 * NFEAT];
    int t = threadIdx.x;  // 0..127
    for (int i = t; i < NFEAT * HID; i += 128) sW[i] = W[i];
    sb[t] = b[t];

    int n0 = blockIdx.x * 256;
    int cnt = NNODES - n0; if (cnt > 256) cnt = 256;
    for (int i = t; i < cnt * NFEAT; i += 128) sAgg[i] = g_agg7[n0 * NFEAT + i];
    __syncthreads();

    for (int r = 0; r < cnt; r++) {
        float acc = sb[t];
#pragma unroll
        for (int k = 0; k < NFEAT; k++)
            acc = fmaf(sAgg[r * NFEAT + k], sW[k * HID + t], acc);
        float o = fmaxf(acc, 0.f);
        size_t idx = (size_t)(n0 + r) * HID + t;
        g_ha[idx]  = o;
        g_h16[idx] = __float2half_rn(o);
    }
}

// ---------------------------------------------------------------------------
// 128-feat gather: warp per node, fp16 neighbor rows, 8-edge unroll (MLP=8)
// ---------------------------------------------------------------------------
__device__ __forceinline__ void acc_edge(float4& acc, uint2 v, float a,
                                         const float4& w, const float4& bb) {
    __half2 h0 = *reinterpret_cast<__half2*>(&v.x);
    __half2 h1 = *reinterpret_cast<__half2*>(&v.y);
    float2 f0 = __half22float2(h0);
    float2 f1 = __half22float2(h1);
    acc.x += fmaxf(f0.x + fmaf(a, w.x, bb.x), 0.f);
    acc.y += fmaxf(f0.y + fmaf(a, w.y, bb.y), 0.f);
    acc.z += fmaxf(f1.x + fmaf(a, w.z, bb.z), 0.f);
    acc.w += fmaxf(f1.y + fmaf(a, w.w, bb.w), 0.f);
}

__global__ void gather128(const float* __restrict__ h32, const float* __restrict__ We,
                          const float* __restrict__ be, float* __restrict__ aggout) {
    int warp = (blockIdx.x * blockDim.x + threadIdx.x) >> 5;
    int lane = threadIdx.x & 31;
    if (warp >= NNODES) return;
    float4 w  = __ldg(&((const float4*)We)[lane]);
    float4 bb = __ldg(&((const float4*)be)[lane]);
    int beg = __ldg(&g_rowptr[warp]);
    int end = __ldg(&g_rowptr[warp + 1]);
    const uint2* h16 = (const uint2*)g_h16;
    float4 acc = ((const float4*)h32)[(size_t)warp * 32 + lane];

    int e = beg;
    for (; e + 7 < end; e += 8) {
        int2 p[8];
#pragma unroll
        for (int i = 0; i < 8; i++) p[i] = __ldg(&g_epack[e + i]);
        uint2 v[8];
#pragma unroll
        for (int i = 0; i < 8; i++) v[i] = __ldg(&h16[(size_t)p[i].x * 32 + lane]);
#pragma unroll
        for (int i = 0; i < 8; i++)
            acc_edge(acc, v[i], __int_as_float(p[i].y), w, bb);
    }
    for (; e + 1 < end; e += 2) {
        int2 p0 = __ldg(&g_epack[e]), p1 = __ldg(&g_epack[e + 1]);
        uint2 v0 = __ldg(&h16[(size_t)p0.x * 32 + lane]);
        uint2 v1 = __ldg(&h16[(size_t)p1.x * 32 + lane]);
        acc_edge(acc, v0, __int_as_float(p0.y), w, bb);
        acc_edge(acc, v1, __int_as_float(p1.y), w, bb);
    }
    if (e < end) {
        int2 p0 = __ldg(&g_epack[e]);
        uint2 v0 = __ldg(&h16[(size_t)p0.x * 32 + lane]);
        acc_edge(acc, v0, __int_as_float(p0.y), w, bb);
    }
    ((float4*)aggout)[(size_t)warp * 32 + lane] = acc;
}

// ---------------------------------------------------------------------------
// TF32 tensor-core dense 128x128 with W-error compensation.
// out[n,:] = relu( A[n,:] @ (W_hi + W_lo) + b ), W_hi = tf32(W), W_lo = tf32(W-W_hi)
// Block: 256 thr (8 warps), tile 128 nodes x 128 cols. Warp tile 64x32.
// ---------------------------------------------------------------------------
#define SA_STRIDE 132
#define SB_STRIDE 136
#define SMEM_TF32 ((128 * SA_STRIDE + 2 * 128 * SB_STRIDE) * 4)

__device__ __forceinline__ unsigned f2tf32(float f) {
    unsigned u;
    asm("cvt.rna.tf32.f32 %0, %1;" : "=r"(u) : "f"(f));
    return u;
}

__device__ __forceinline__ void mma8(float4& d, const unsigned a[4], const unsigned b[2]) {
    asm volatile(
        "mma.sync.aligned.m16n8k8.row.col.f32.tf32.tf32.f32 "
        "{%0,%1,%2,%3}, {%4,%5,%6,%7}, {%8,%9}, {%0,%1,%2,%3};\n"
        : "+f"(d.x), "+f"(d.y), "+f"(d.z), "+f"(d.w)
        : "r"(a[0]), "r"(a[1]), "r"(a[2]), "r"(a[3]), "r"(b[0]), "r"(b[1]));
}

__global__ void __launch_bounds__(256, 1)
dense128_tf32(const float* __restrict__ A, const float* __restrict__ W,
              const float* __restrict__ b, float* __restrict__ out,
              int write16) {
    extern __shared__ float sm[];
    float* sA   = sm;                        // 128 x SA_STRIDE
    float* sBhi = sm + 128 * SA_STRIDE;      // 128 x SB_STRIDE (k-major)
    float* sBlo = sBhi + 128 * SB_STRIDE;

    int t = threadIdx.x;
    int m0 = blockIdx.x * 128;

    // Stage W -> tf32 hi/lo
    {
        const float4* W4 = (const float4*)W;
        for (int i = t; i < 128 * 32; i += 256) {
            int k = i >> 5, c4 = i & 31;
            float4 w = __ldg(&W4[k * 32 + c4]);
            float4 hi, lo;
            hi.x = __uint_as_float(f2tf32(w.x)); lo.x = __uint_as_float(f2tf32(w.x - hi.x));
            hi.y = __uint_as_float(f2tf32(w.y)); lo.y = __uint_as_float(f2tf32(w.y - hi.y));
            hi.z = __uint_as_float(f2tf32(w.z)); lo.z = __uint_as_float(f2tf32(w.z - hi.z));
            hi.w = __uint_as_float(f2tf32(w.w)); lo.w = __uint_as_float(f2tf32(w.w - hi.w));
            *(float4*)(sBhi + k * SB_STRIDE + c4 * 4) = hi;
            *(float4*)(sBlo + k * SB_STRIDE + c4 * 4) = lo;
        }
    }
    // Stage A tile -> tf32
    {
        const float4* A4 = (const float4*)A;
        for (int i = t; i < 128 * 32; i += 256) {
            int r = i >> 5, c4 = i & 31;
            int n = m0 + r;
            float4 v = make_float4(0.f, 0.f, 0.f, 0.f);
            if (n < NNODES) v = __ldg(&A4[(size_t)n * 32 + c4]);
            v.x = __uint_as_float(f2tf32(v.x));
            v.y = __uint_as_float(f2tf32(v.y));
            v.z = __uint_as_float(f2tf32(v.z));
            v.w = __uint_as_float(f2tf32(v.w));
            *(float4*)(sA + r * SA_STRIDE + c4 * 4) = v;
        }
    }
    __syncthreads();

    int lane = t & 31, wid = t >> 5;
    int gid = lane >> 2, tig = lane & 3;
    int rowbase = (wid & 1) * 64;      // warp_m in {0,1}
    int colbase = (wid >> 1) * 32;     // warp_n in {0..3}

    float4 acc[4][4];
#pragma unroll
    for (int i = 0; i < 4; i++)
#pragma unroll
        for (int j = 0; j < 4; j++) acc[i][j] = make_float4(0.f, 0.f, 0.f, 0.f);

#pragma unroll 2
    for (int ks = 0; ks < 16; ks++) {
        unsigned a[4][4];
#pragma unroll
        for (int mf = 0; mf < 4; mf++) {
            const float* pa = sA + (rowbase + mf * 16 + gid) * SA_STRIDE + ks * 8 + tig;
            a[mf][0] = __float_as_uint(pa[0]);
            a[mf][1] = __float_as_uint(pa[8 * SA_STRIDE]);
            a[mf][2] = __float_as_uint(pa[4]);
            a[mf][3] = __float_as_uint(pa[8 * SA_STRIDE + 4]);
        }
        unsigned bh[4][2], bl[4][2];
#pragma unroll
        for (int nf = 0; nf < 4; nf++) {
            int off = (ks * 8 + tig) * SB_STRIDE + colbase + nf * 8 + gid;
            bh[nf][0] = __float_as_uint(sBhi[off]);
            bh[nf][1] = __float_as_uint(sBhi[off + 4 * SB_STRIDE]);
            bl[nf][0] = __float_as_uint(sBlo[off]);
            bl[nf][1] = __float_as_uint(sBlo[off + 4 * SB_STRIDE]);
        }
#pragma unroll
        for (int mf = 0; mf < 4; mf++)
#pragma unroll
            for (int nf = 0; nf < 4; nf++) {
                mma8(acc[mf][nf], a[mf], bh[nf]);
                mma8(acc[mf][nf], a[mf], bl[nf]);
            }
    }

    // Epilogue: bias + relu, fp32 out (+ optional fp16 mirror)
#pragma unroll
    for (int nf = 0; nf < 4; nf++) {
        int col = colbase + nf * 8 + tig * 2;
        float bx = __ldg(&b[col]), by = __ldg(&b[col + 1]);
#pragma unroll
        for (int mf = 0; mf < 4; mf++) {
            int r0 = m0 + rowbase + mf * 16 + gid;
            int r1 = r0 + 8;
            float4 v = acc[mf][nf];
            if (r0 < NNODES) {
                float2 o = make_float2(fmaxf(v.x + bx, 0.f), fmaxf(v.y + by, 0.f));
                *(float2*)(out + (size_t)r0 * HID + col) = o;
                if (write16) {
                    __half2 h = __floats2half2_rn(o.x, o.y);
                    *(unsigned*)((__half*)g_h16 + (size_t)r0 * HID + col) =
                        *reinterpret_cast<unsigned*>(&h);
                }
            }
            if (r1 < NNODES) {
                float2 o = make_float2(fmaxf(v.z + bx, 0.f), fmaxf(v.w + by, 0.f));
                *(float2*)(out + (size_t)r1 * HID + col) = o;
                if (write16) {
                    __half2 h = __floats2half2_rn(o.x, o.y);
                    *(unsigned*)((__half*)g_h16 + (size_t)r1 * HID + col) =
                        *reinterpret_cast<unsigned*>(&h);
                }
            }
        }
    }
}

// ---------------------------------------------------------------------------
// Pooling + head
// ---------------------------------------------------------------------------
__global__ void pool_init() {
    int t = blockIdx.x * blockDim.x + threadIdx.x;
    if (t < NGRAPH * HID) g_pool[t] = 0.f;
    if (t < NGRAPH) g_cnt[t] = 0.f;
}

__global__ void pool_kernel(const float* __restrict__ h, const int* __restrict__ batch) {
    int f = threadIdx.x;  // 0..127
    int n0 = blockIdx.x * 256;
    int n1 = n0 + 256; if (n1 > NNODES) n1 = NNODES;
    if (n0 >= NNODES) return;
    float acc = 0.f, c = 0.f;
    int curg = batch[n0];
    for (int n = n0; n < n1; n++) {
        int g = batch[n];
        if (g != curg) {
            atomicAdd(&g_pool[curg * HID + f], acc);
            if (f == 0) atomicAdd(&g_cnt[curg], c);
            acc = 0.f; c = 0.f; curg = g;
        }
        acc += h[(size_t)n * HID + f];
        c += 1.f;
    }
    atomicAdd(&g_pool[curg * HID + f], acc);
    if (f == 0) atomicAdd(&g_cnt[curg], c);
}

__global__ void final_kernel(const float* __restrict__ Wlin, const float* __restrict__ blin,
                             float* __restrict__ out) {
    int t = threadIdx.x;
    if (t >= NGRAPH * NCLASS) return;
    int g = t / NCLASS, c = t % NCLASS;
    float cnt = fmaxf(g_cnt[g], 1.f);
    float acc = blin[c];
#pragma unroll 8
    for (int f = 0; f < HID; f++)
        acc = fmaf(g_pool[g * HID + f] / cnt, Wlin[f * NCLASS + c], acc);
    out[t] = acc;
}

// ---------------------------------------------------------------------------
// Launch
// ---------------------------------------------------------------------------
extern "C" void kernel_launch(void* const* d_in, const int* in_sizes, int n_in,
                              void* d_out, int out_size) {
    const float* x     = (const float*)d_in[0];
    const int*   ei    = (const int*)d_in[1];
    const float* ea    = (const float*)d_in[2];
    const int*   batch = (const int*)d_in[3];
    const float* We1 = (const float*)d_in[4],  *be1 = (const float*)d_in[5];
    const float* W1  = (const float*)d_in[6],  *b1  = (const float*)d_in[7];
    const float* We2 = (const float*)d_in[8],  *be2 = (const float*)d_in[9];
    const float* W2  = (const float*)d_in[10], *b2  = (const float*)d_in[11];
    const float* We3 = (const float*)d_in[12], *be3 = (const float*)d_in[13];
    const float* W3  = (const float*)d_in[14], *b3  = (const float*)d_in[15];
    const float* Wlin = (const float*)d_in[16], *blin = (const float*)d_in[17];
    float* out = (float*)d_out;

    void *aggp, *hap, *hbp, *curp;
    cudaGetSymbolAddress(&aggp, g_agg);
    cudaGetSymbolAddress(&hap,  g_ha);
    cudaGetSymbolAddress(&hbp,  g_hb);
    cudaGetSymbolAddress(&curp, g_cur);
    float* agg = (float*)aggp;
    float* ha  = (float*)hap;
    float* hb  = (float*)hbp;

    cudaFuncSetAttribute(dense128_tf32, cudaFuncAttributeMaxDynamicSharedMemorySize, SMEM_TF32);

    const int EBLK = (NEDGES + 255) / 256;
    const int G128_BLOCKS = (NNODES * 32 + 255) / 256;   // warp per node
    const int DT_BLOCKS   = (NNODES + 127) / 128;

    // CSR build (reused by all 3 layers)
    cudaMemsetAsync(curp, 0, NNODES * sizeof(int), 0);
    hist_kernel<<<EBLK, 256>>>(ei);
    scan_kernel<<<1, 1024>>>();
    fill_kernel<<<EBLK, 256>>>(ei, ea);

    // Layer 1 (in = 7 feats)
    gather7<<<(NNODES + 255) / 256, 256>>>(x, We1, be1);
    dense7<<<(NNODES + 255) / 256, 128>>>(W1, b1);                   // -> g_ha + g_h16

    // Layer 2
    gather128<<<G128_BLOCKS, 256>>>(ha, We2, be2, agg);              // reads g_h16 (h1)
    dense128_tf32<<<DT_BLOCKS, 256, SMEM_TF32>>>(agg, W2, b2, hb, 1);// -> g_hb + g_h16

    // Layer 3
    gather128<<<G128_BLOCKS, 256>>>(hb, We3, be3, agg);              // reads g_h16 (h2)
    dense128_tf32<<<DT_BLOCKS, 256, SMEM_TF32>>>(agg, W3, b3, ha, 0);// -> g_ha

    // Mean pool + linear head
    pool_init<<<8, 128>>>();
    pool_kernel<<<(NNODES + 255) / 256, 128>>>(ha, batch);
    final_kernel<<<1, 64>>>(Wlin, blin, out);
}